// round 1
// baseline (speedup 1.0000x reference)
#include <cuda_runtime.h>

typedef unsigned long long u64;

// ---------- f32x2 packed helpers (Blackwell sm_103a) ----------
__device__ __forceinline__ u64 pk2(float lo, float hi) {
    u64 r; asm("mov.b64 %0,{%1,%2};" : "=l"(r) : "f"(lo), "f"(hi)); return r;
}
__device__ __forceinline__ void unpk2(u64 v, float& lo, float& hi) {
    asm("mov.b64 {%0,%1},%2;" : "=f"(lo), "=f"(hi) : "l"(v));
}
__device__ __forceinline__ u64 fma2(u64 a, u64 b, u64 c) {
    u64 d; asm("fma.rn.f32x2 %0,%1,%2,%3;" : "=l"(d) : "l"(a), "l"(b), "l"(c)); return d;
}
__device__ __forceinline__ u64 add2(u64 a, u64 b) {
    u64 d; asm("add.rn.f32x2 %0,%1,%2;" : "=l"(d) : "l"(a), "l"(b)); return d;
}
__device__ __forceinline__ u64 mul2(u64 a, u64 b) {
    u64 d; asm("mul.rn.f32x2 %0,%1,%2;" : "=l"(d) : "l"(a), "l"(b)); return d;
}

// ---------- fast-but-accurate activations (EX2 + RCP, ~2^-22 rel err) ----------
__device__ __forceinline__ float ex2a(float x) {
    float y; asm("ex2.approx.f32 %0,%1;" : "=f"(y) : "f"(x)); return y;
}
__device__ __forceinline__ float rcpa(float x) {
    float y; asm("rcp.approx.f32 %0,%1;" : "=f"(y) : "f"(x)); return y;
}
__device__ __forceinline__ float sigm(float x) {
    // 1/(1+exp(-x)) = rcp(1 + 2^(-x*log2e))
    return rcpa(1.0f + ex2a(x * -1.4426950408889634f));
}
__device__ __forceinline__ float tanha(float x) {
    // tanh(x) = 2*sigmoid(2x) - 1
    return fmaf(2.0f, rcpa(1.0f + ex2a(x * -2.8853900817779268f)), -1.0f);
}

// H = 20 hidden units (layer 1), O = 1 (layer 2). One warp per batch row.
// Lane j (< 20) owns hidden unit j: computes gates i_j, f_j, g_j, o_j.
// Gate accumulators packed f32x2 as (i,f) and (g,o).
__global__ void __launch_bounds__(128)
lstm_warp_kernel(const float* __restrict__ xin,
                 const float* __restrict__ Wih1, const float* __restrict__ Whh1,
                 const float* __restrict__ bih1, const float* __restrict__ bhh1,
                 const float* __restrict__ Wih2, const float* __restrict__ Whh2,
                 const float* __restrict__ bih2, const float* __restrict__ bhh2,
                 float* __restrict__ out, int B, int T, int F)
{
    const int w    = threadIdx.x >> 5;
    const int lane = threadIdx.x & 31;
    const int b    = blockIdx.x * 4 + w;

    // per-warp double-buffered h1 broadcast buffer, values stored duplicated (h,h)
    __shared__ __align__(16) u64 hbuf[4][2][32];

    if (b >= B) return;

    // ---- load per-lane weights into registers (one time) ----
    const int jj = (lane < 20) ? lane : (lane - 20);   // clamp: lanes 20..31 mirror valid lanes

    u64 wif[20], wgo[20];
#pragma unroll
    for (int k = 0; k < 20; k++) {
        wif[k] = pk2(Whh1[jj * 20 + k],        Whh1[(20 + jj) * 20 + k]);
        wgo[k] = pk2(Whh1[(40 + jj) * 20 + k], Whh1[(60 + jj) * 20 + k]);
    }
    const u64 wxif = pk2(Wih1[jj],      Wih1[20 + jj]);
    const u64 wxgo = pk2(Wih1[40 + jj], Wih1[60 + jj]);
    const u64 bif  = pk2(bih1[jj] + bhh1[jj],           bih1[20 + jj] + bhh1[20 + jj]);
    const u64 bgo  = pk2(bih1[40 + jj] + bhh1[40 + jj], bih1[60 + jj] + bhh1[60 + jj]);

    // layer-2 per-lane columns; zero on the 12 inactive lanes so the butterfly is exact
    u64 uif = 0ull, ugo = 0ull;
    if (lane < 20) {
        uif = pk2(Wih2[lane],      Wih2[20 + lane]);
        ugo = pk2(Wih2[40 + lane], Wih2[60 + lane]);
    }
    const u64 whh2if = pk2(Whh2[0], Whh2[1]);
    const u64 whh2go = pk2(Whh2[2], Whh2[3]);
    const u64 b2if   = pk2(bih2[0] + bhh2[0], bih2[1] + bhh2[1]);
    const u64 b2go   = pk2(bih2[2] + bhh2[2], bih2[3] + bhh2[3]);

    // ---- state ----
    float c1 = 0.0f, h1 = 0.0f, c2 = 0.0f, h2 = 0.0f;
    int p = 0;
    hbuf[w][0][lane] = 0ull;
    __syncwarp();

    // ---- one recurrence step (both layers) ----
    auto stepf = [&](float x) {
        const u64 xx  = pk2(x, x);
        u64 aif = fma2(wxif, xx, bif);
        u64 ago = fma2(wxgo, xx, bgo);
        const ulonglong2* hp = (const ulonglong2*)hbuf[w][p];
#pragma unroll
        for (int m = 0; m < 10; m++) {
            ulonglong2 hv = hp[m];               // LDS.128, broadcast
            aif = fma2(wif[2 * m],     hv.x, aif);
            ago = fma2(wgo[2 * m],     hv.x, ago);
            aif = fma2(wif[2 * m + 1], hv.y, aif);
            ago = fma2(wgo[2 * m + 1], hv.y, ago);
        }
        float gi, gf, gg, go; unpk2(aif, gi, gf); unpk2(ago, gg, go);
        const float si = sigm(gi), sf = sigm(gf), tg = tanha(gg), so = sigm(go);
        c1 = fmaf(sf, c1, si * tg);
        h1 = so * tanha(c1);
        hbuf[w][p ^ 1][lane] = pk2(h1, h1);      // STS.64 to the other buffer

        // ---- layer 2 (input = c1, scalar hidden) ----
        const u64 cc = pk2(c1, c1);
        u64 pif = mul2(uif, cc);
        u64 pgo = mul2(ugo, cc);
#pragma unroll
        for (int mm = 16; mm > 0; mm >>= 1) {
            pif = add2(pif, __shfl_xor_sync(0xffffffffu, pif, mm));
            pgo = add2(pgo, __shfl_xor_sync(0xffffffffu, pgo, mm));
        }
        const u64 hh = pk2(h2, h2);
        pif = fma2(whh2if, hh, add2(pif, b2if));
        pgo = fma2(whh2go, hh, add2(pgo, b2go));
        float qi, qf, qg, qo; unpk2(pif, qi, qf); unpk2(pgo, qg, qo);
        const float s2i = sigm(qi), s2f = sigm(qf), t2g = tanha(qg), s2o = sigm(qo);
        c2 = fmaf(s2f, c2, s2i * t2g);
        h2 = s2o * tanha(c2);

        __syncwarp();   // orders this step's STS before next step's LDS
        p ^= 1;
    };

    const float* xrow = xin + (size_t)b * T;
    float*       orow = out + (size_t)b * (T + F);

    // ---- main sequence ----
    int t = 0;
    if ((T & 3) == 0) {
        const float4* xv4 = (const float4*)xrow;
        float4*       ov4 = (float4*)orow;
#pragma unroll 1
        for (int t4 = 0; t4 < (T >> 2); t4++) {
            const float4 xv = xv4[t4];            // broadcast LDG.128
            float4 ov;
            stepf(xv.x); ov.x = c2;
            stepf(xv.y); ov.y = c2;
            stepf(xv.z); ov.z = c2;
            stepf(xv.w); ov.w = c2;
            if (lane == 0) ov4[t4] = ov;          // STG.128 every 4 steps
        }
        t = T;
    }
#pragma unroll 1
    for (; t < T; t++) { stepf(xrow[t]); if (lane == 0) orow[t] = c2; }

    // ---- autoregressive future: x <- c2 (replicated in all lanes) ----
    int f = 0;
    if (((T & 3) == 0) && ((F & 3) == 0)) {
        float4* ov4 = (float4*)(orow + T);
#pragma unroll 1
        for (int q = 0; q < (F >> 2); q++) {
            float4 ov;
            stepf(c2); ov.x = c2;
            stepf(c2); ov.y = c2;
            stepf(c2); ov.z = c2;
            stepf(c2); ov.w = c2;
            if (lane == 0) ov4[q] = ov;
        }
        f = F;
    }
#pragma unroll 1
    for (; f < F; f++) { stepf(c2); if (lane == 0) orow[T + f] = c2; }
}

extern "C" void kernel_launch(void* const* d_in, const int* in_sizes, int n_in,
                              void* d_out, int out_size)
{
    const float* xin  = (const float*)d_in[0];
    const float* Wih1 = (const float*)d_in[1];
    const float* Whh1 = (const float*)d_in[2];
    const float* bih1 = (const float*)d_in[3];
    const float* bhh1 = (const float*)d_in[4];
    const float* Wih2 = (const float*)d_in[5];
    const float* Whh2 = (const float*)d_in[6];
    const float* bih2 = (const float*)d_in[7];
    const float* bhh2 = (const float*)d_in[8];
    // d_in[9] ("future") is a device scalar; F is derived from out_size instead.

    const int B = 1024;
    const int T = in_sizes[0] / B;          // 4096
    const int F = out_size / B - T;         // 16

    dim3 grid((B + 3) / 4), block(128);
    lstm_warp_kernel<<<grid, block>>>(xin, Wih1, Whh1, bih1, bhh1,
                                      Wih2, Whh2, bih2, bhh2,
                                      (float*)d_out, B, T, F);
}

// round 3
// speedup vs baseline: 1.1627x; 1.1627x over previous
#include <cuda_runtime.h>

typedef unsigned long long u64;

// ---------- f32x2 packed helpers (Blackwell sm_103a) ----------
__device__ __forceinline__ u64 pk2(float lo, float hi) {
    u64 r; asm("mov.b64 %0,{%1,%2};" : "=l"(r) : "f"(lo), "f"(hi)); return r;
}
__device__ __forceinline__ void unpk2(u64 v, float& lo, float& hi) {
    asm("mov.b64 {%0,%1},%2;" : "=f"(lo), "=f"(hi) : "l"(v));
}
__device__ __forceinline__ u64 fma2(u64 a, u64 b, u64 c) {
    u64 d; asm("fma.rn.f32x2 %0,%1,%2,%3;" : "=l"(d) : "l"(a), "l"(b), "l"(c)); return d;
}
__device__ __forceinline__ u64 add2(u64 a, u64 b) {
    u64 d; asm("add.rn.f32x2 %0,%1,%2;" : "=l"(d) : "l"(a), "l"(b)); return d;
}
__device__ __forceinline__ u64 mul2(u64 a, u64 b) {
    u64 d; asm("mul.rn.f32x2 %0,%1,%2;" : "=l"(d) : "l"(a), "l"(b)); return d;
}

// ---------- fast-but-accurate activations (EX2 + RCP, ~2^-22 rel err) ----------
__device__ __forceinline__ float ex2a(float x) {
    float y; asm("ex2.approx.f32 %0,%1;" : "=f"(y) : "f"(x)); return y;
}
__device__ __forceinline__ float rcpa(float x) {
    float y; asm("rcp.approx.f32 %0,%1;" : "=f"(y) : "f"(x)); return y;
}
__device__ __forceinline__ float sigm(float x) {
    return rcpa(1.0f + ex2a(x * -1.4426950408889634f));
}
__device__ __forceinline__ float tanha(float x) {
    return fmaf(2.0f, rcpa(1.0f + ex2a(x * -2.8853900817779268f)), -1.0f);
}

// One warp per batch row. Lane j (<20) owns hidden unit j of layer 1;
// gates packed f32x2 as (i,f),(g,o). Layer 2 (O=1) via SHFL butterfly,
// SOFTWARE-PIPELINED one step behind layer 1 in the main phase so its
// reduction latency hides under layer 1's recurrence chain.
__global__ void __launch_bounds__(128)
lstm_warp_kernel(const float* __restrict__ xin,
                 const float* __restrict__ Wih1, const float* __restrict__ Whh1,
                 const float* __restrict__ bih1, const float* __restrict__ bhh1,
                 const float* __restrict__ Wih2, const float* __restrict__ Whh2,
                 const float* __restrict__ bih2, const float* __restrict__ bhh2,
                 float* __restrict__ out, int B, int T, int F)
{
    const int w    = threadIdx.x >> 5;
    const int lane = threadIdx.x & 31;
    const int b    = blockIdx.x * 4 + w;

    // per-warp double-buffered h1 broadcast buffer, values stored duplicated (h,h)
    __shared__ __align__(16) u64 hbuf[4][2][32];

    if (b >= B) return;

    // ---- per-lane layer-1 weights in registers ----
    const int jj = (lane < 20) ? lane : (lane - 20);

    u64 wif[20], wgo[20];
#pragma unroll
    for (int k = 0; k < 20; k++) {
        wif[k] = pk2(Whh1[jj * 20 + k],        Whh1[(20 + jj) * 20 + k]);
        wgo[k] = pk2(Whh1[(40 + jj) * 20 + k], Whh1[(60 + jj) * 20 + k]);
    }
    const u64 wxif = pk2(Wih1[jj],      Wih1[20 + jj]);
    const u64 wxgo = pk2(Wih1[40 + jj], Wih1[60 + jj]);
    const u64 bif  = pk2(bih1[jj] + bhh1[jj],           bih1[20 + jj] + bhh1[20 + jj]);
    const u64 bgo  = pk2(bih1[40 + jj] + bhh1[40 + jj], bih1[60 + jj] + bhh1[60 + jj]);

    // layer-2: per-lane input-weight columns (zeroed on inactive lanes -> exact reduction)
    u64 uif = 0ull, ugo = 0ull;
    if (lane < 20) {
        uif = pk2(Wih2[lane],      Wih2[20 + lane]);
        ugo = pk2(Wih2[40 + lane], Wih2[60 + lane]);
    }
    const float wh2i = Whh2[0], wh2f = Whh2[1], wh2g = Whh2[2], wh2o = Whh2[3];
    const float b2i = bih2[0] + bhh2[0], b2f = bih2[1] + bhh2[1];
    const float b2g = bih2[2] + bhh2[2], b2o = bih2[3] + bhh2[3];

    // ---- state ----
    float c1 = 0.0f, c2 = 0.0f, h2s = 0.0f;
    int p = 0;
    hbuf[w][0][lane] = 0ull;
    __syncwarp();

    // ---- layer 1: one recurrence step (critical chain) ----
    auto layer1 = [&](float x) {
        __syncwarp();                            // order prev STS before this LDS
        const ulonglong2* hp = (const ulonglong2*)hbuf[w][p];
        const u64 xx = pk2(x, x);
        const ulonglong2 v0 = hp[0], v1 = hp[1];
        // 4 accumulator chains per gate pair (depth ~6)
        u64 aA = fma2(wif[0], v0.x, fma2(wxif, xx, bif));
        u64 gA = fma2(wgo[0], v0.x, fma2(wxgo, xx, bgo));
        u64 aB = mul2(wif[1], v0.y), gB = mul2(wgo[1], v0.y);
        u64 aC = mul2(wif[2], v1.x), gC = mul2(wgo[2], v1.x);
        u64 aD = mul2(wif[3], v1.y), gD = mul2(wgo[3], v1.y);
#pragma unroll
        for (int j = 2; j < 10; j += 2) {
            const ulonglong2 va = hp[j], vb = hp[j + 1];
            aA = fma2(wif[2 * j],     va.x, aA);  gA = fma2(wgo[2 * j],     va.x, gA);
            aB = fma2(wif[2 * j + 1], va.y, aB);  gB = fma2(wgo[2 * j + 1], va.y, gB);
            aC = fma2(wif[2 * j + 2], vb.x, aC);  gC = fma2(wgo[2 * j + 2], vb.x, gC);
            aD = fma2(wif[2 * j + 3], vb.y, aD);  gD = fma2(wgo[2 * j + 3], vb.y, gD);
        }
        const u64 aif = add2(add2(aA, aB), add2(aC, aD));
        const u64 ago = add2(add2(gA, gB), add2(gC, gD));
        float gi, gf, gg, go; unpk2(aif, gi, gf); unpk2(ago, gg, go);
        const float sf = sigm(gf), si = sigm(gi), tg = tanha(gg), so = sigm(go);
        c1 = fmaf(sf, c1, si * tg);
        const float h1v = so * tanha(c1);
        hbuf[w][p ^ 1][lane] = pk2(h1v, h1v);    // STS.64 to the other buffer
        p ^= 1;
    };

    // ---- layer 2 front: per-lane products + 5-level f32x2 butterfly ----
    auto layer2_front = [&](float c1v, u64& pif, u64& pgo) {
        const u64 cc = pk2(c1v, c1v);
        pif = mul2(uif, cc);
        pgo = mul2(ugo, cc);
#pragma unroll
        for (int mm = 16; mm; mm >>= 1) {
            pif = add2(pif, __shfl_xor_sync(0xffffffffu, pif, mm));
            pgo = add2(pgo, __shfl_xor_sync(0xffffffffu, pgo, mm));
        }
    };
    // ---- layer 2 back: activations + (c2, h2) update ----
    auto layer2_back = [&](u64 pif, u64 pgo) {
        float r0, r1, r2, r3; unpk2(pif, r0, r1); unpk2(pgo, r2, r3);
        const float s2i = sigm(r0 + fmaf(h2s, wh2i, b2i));
        const float s2f = sigm(r1 + fmaf(h2s, wh2f, b2f));
        const float t2g = tanha(r2 + fmaf(h2s, wh2g, b2g));
        const float s2o = sigm(r3 + fmaf(h2s, wh2o, b2o));
        c2  = fmaf(s2f, c2, s2i * t2g);
        h2s = s2o * tanha(c2);
    };

    const float* xrow = xin + (size_t)b * T;
    float*       orow = out + (size_t)b * (T + F);

    // ---- main sequence: layer 2 pipelined one step behind layer 1 ----
    layer1(xrow[0]);
    float c1p = c1;
#pragma unroll 1
    for (int t = 1; t < T; t++) {
        const float x = xrow[t];
        u64 pif, pgo;
        layer2_front(c1p, pif, pgo);   // butterfly for step t-1 ...
        layer1(x);                     // ... overlaps layer-1 of step t
        layer2_back(pif, pgo);
        if (lane == 0) orow[t - 1] = c2;
        c1p = c1;
    }
    {   // flush the pipeline: layer 2 for step T-1
        u64 pif, pgo;
        layer2_front(c1p, pif, pgo);
        layer2_back(pif, pgo);
        if (lane == 0) orow[T - 1] = c2;
    }

    // ---- autoregressive future: x <- c2, strictly sequential ----
#pragma unroll 1
    for (int f = 0; f < F; f++) {
        layer1(c2);                    // c2 is warp-uniform (butterfly broadcast)
        u64 pif, pgo;
        layer2_front(c1, pif, pgo);
        layer2_back(pif, pgo);
        if (lane == 0) orow[T + f] = c2;
    }
}

extern "C" void kernel_launch(void* const* d_in, const int* in_sizes, int n_in,
                              void* d_out, int out_size)
{
    const float* xin  = (const float*)d_in[0];
    const float* Wih1 = (const float*)d_in[1];
    const float* Whh1 = (const float*)d_in[2];
    const float* bih1 = (const float*)d_in[3];
    const float* bhh1 = (const float*)d_in[4];
    const float* Wih2 = (const float*)d_in[5];
    const float* Whh2 = (const float*)d_in[6];
    const float* bih2 = (const float*)d_in[7];
    const float* bhh2 = (const float*)d_in[8];

    const int B = 1024;
    const int T = in_sizes[0] / B;          // 4096
    const int F = out_size / B - T;         // 16

    dim3 grid((B + 3) / 4), block(128);
    lstm_warp_kernel<<<grid, block>>>(xin, Wih1, Whh1, bih1, bhh1,
                                      Wih2, Whh2, bih2, bhh2,
                                      (float*)d_out, B, T, F);
}